// round 16
// baseline (speedup 1.0000x reference)
#include <cuda_runtime.h>
#include <cuda_bf16.h>
#include <math.h>
#include <stdint.h>

// Problem constants (DEPTH=2, but reference returns only last layer's output
// computed from the ORIGINAL x, so we evaluate ONLY layer index 1).
#define BATCH 2
#define SEQ   2048
#define DIM   256
#define MLPD  1024
#define HEADS 8
#define HD    32
#define ROWS  (BATCH*SEQ)          // 4096
#define LAYER 1

// ------------------------- scratch (device globals) -------------------------
__device__ __nv_bfloat16 g_ybf   [ROWS*DIM];       // ln1 out (bf16)
__device__ __nv_bfloat16 g_qkvbf [ROWS*3*DIM];     // qkv (bf16)
__device__ __nv_bfloat16 g_vt    [BATCH*HEADS*HD*SEQ]; // V transposed per (b,h): [bh][32][2048]
__device__ __nv_bfloat16 g_attnbf[ROWS*DIM];       // attention out (bf16)
__device__ float         g_a     [ROWS*DIM];       // attn residual (fp32)
__device__ __nv_bfloat16 g_zbf   [ROWS*DIM];       // ln2 out (bf16)
__device__ __nv_bfloat16 g_hbf   [ROWS*MLPD];      // mlp hidden (bf16)
// transposed bf16 weights  [N][K]
__device__ __nv_bfloat16 g_WqkvT [3*DIM*DIM];
__device__ __nv_bfloat16 g_WoT   [DIM*DIM];
__device__ __nv_bfloat16 g_W1T   [MLPD*DIM];
__device__ __nv_bfloat16 g_W2T   [DIM*MLPD];

// ----------------------------- helpers --------------------------------------
__device__ __forceinline__ void cp16(void* sdst, const void* gsrc) {
    uint32_t s = (uint32_t)__cvta_generic_to_shared(sdst);
    asm volatile("cp.async.cg.shared.global [%0], [%1], 16;"
                 :: "r"(s), "l"(gsrc) : "memory");
}
__device__ __forceinline__ void cp_commit() {
    asm volatile("cp.async.commit_group;" ::: "memory");
}
__device__ __forceinline__ void mma16816(float* c, const uint32_t* a,
                                         const uint32_t* b) {
    asm volatile(
        "mma.sync.aligned.m16n8k16.row.col.f32.bf16.bf16.f32 "
        "{%0,%1,%2,%3}, {%4,%5,%6,%7}, {%8,%9}, {%0,%1,%2,%3};"
        : "+f"(c[0]), "+f"(c[1]), "+f"(c[2]), "+f"(c[3])
        : "r"(a[0]), "r"(a[1]), "r"(a[2]), "r"(a[3]), "r"(b[0]), "r"(b[1]));
}
__device__ __forceinline__ uint32_t pk(float lo, float hi) {
    __nv_bfloat162 t = __floats2bfloat162_rn(lo, hi);
    return *(uint32_t*)&t;
}

// output store helpers
__device__ __forceinline__ void stv(float* p, float v) { *p = v; }
__device__ __forceinline__ void stv(__nv_bfloat16* p, float v) { *p = __float2bfloat16(v); }

// ------------------------------ LayerNorm -----------------------------------
template <typename OT>
__global__ void ln_kernel(const float* __restrict__ x,
                          const float* __restrict__ gamma,
                          const float* __restrict__ beta,
                          OT* __restrict__ y)
{
    int row = blockIdx.x;
    int tid = threadIdx.x;
    float v = x[(size_t)row * DIM + tid];

    float s = v, sq = v * v;
    #pragma unroll
    for (int o = 16; o; o >>= 1) {
        s  += __shfl_xor_sync(0xffffffffu, s,  o);
        sq += __shfl_xor_sync(0xffffffffu, sq, o);
    }
    __shared__ float red[2][8];
    int w = tid >> 5, l = tid & 31;
    if (l == 0) { red[0][w] = s; red[1][w] = sq; }
    __syncthreads();
    float st = 0.f, sqt = 0.f;
    #pragma unroll
    for (int i = 0; i < 8; i++) { st += red[0][i]; sqt += red[1][i]; }
    float mean = st * (1.0f / DIM);
    float var  = sqt * (1.0f / DIM) - mean * mean;
    float inv  = rsqrtf(var + 1e-5f);
    stv(&y[(size_t)row * DIM + tid], (v - mean) * inv * gamma[tid] + beta[tid]);
}

// -------------------- weight transpose+convert (fp32->bf16) ------------------
__global__ void transpose_bf16(const float* __restrict__ in,
                               __nv_bfloat16* __restrict__ out,
                               int R, int C)
{
    __shared__ float t[32][33];
    int c0 = blockIdx.x * 32, r0 = blockIdx.y * 32;
    int tx = threadIdx.x, ty = threadIdx.y;   // (32, 8)
    #pragma unroll
    for (int i = 0; i < 32; i += 8)
        t[ty + i][tx] = in[(size_t)(r0 + ty + i) * C + c0 + tx];
    __syncthreads();
    #pragma unroll
    for (int i = 0; i < 32; i += 8)
        out[(size_t)(c0 + ty + i) * R + r0 + tx] = __float2bfloat16(t[tx][ty + i]);
}

// ------------------- V transpose: qkv bf16 -> Vt[bh][32][2048] ---------------
__global__ void transpose_v(const __nv_bfloat16* __restrict__ qkvbf,
                            __nv_bfloat16* __restrict__ vt)
{
    __shared__ __nv_bfloat16 t[64][33];
    int bh = blockIdx.y, b = bh >> 3, h = bh & 7;
    int n0 = blockIdx.x * 64;
    int tx = threadIdx.x, ty = threadIdx.y;   // (32, 8)
    #pragma unroll
    for (int i = 0; i < 8; i++) {
        int n = ty + i * 8;
        t[n][tx] = qkvbf[((size_t)(b * SEQ + n0 + n)) * (3 * DIM) + 2 * DIM + h * HD + tx];
    }
    __syncthreads();
    #pragma unroll
    for (int dd = 0; dd < 4; dd++) {
        int d = ty + dd * 8;
        vt[((size_t)(bh * HD + d)) * SEQ + n0 + tx]      = t[tx][d];
        vt[((size_t)(bh * HD + d)) * SEQ + n0 + 32 + tx] = t[tx + 32][d];
    }
}

// ------------------------- mma.sync bf16 GEMM --------------------------------
// C[M,N] = A[M,K] @ Bt[N,K]^T + bias[N]  (+ epilogue)
// EPI: 0 = bias, 1 = bias + exact GELU, 2 = bias + residual
#define BM 128
#define BN 64
#define BK 32
#define ASTR 40   // bf16 elems per smem row (32 data + 8 pad) -> 80B stride
template <int EPI, typename OT>
__global__ void __launch_bounds__(256) gemm_mma(
    const __nv_bfloat16* __restrict__ A,
    const __nv_bfloat16* __restrict__ Bt,
    const float* __restrict__ bias,
    const float* __restrict__ res,
    OT* __restrict__ C,
    int M, int N, int K)
{
    __shared__ __nv_bfloat16 As[2][BM * ASTR];
    __shared__ __nv_bfloat16 Bs[2][BN * ASTR];

    int tid = threadIdx.x;
    int wid = tid >> 5, lane = tid & 31;
    int wm = wid & 3, wn = wid >> 2;     // 4 x 2 warp grid
    int g = lane >> 2, tig = lane & 3;
    int bm = blockIdx.y * BM, bn = blockIdx.x * BN;

    int crow = tid >> 2;
    int ccol = (tid & 3) * 8;

    float c[2][4][4];
    #pragma unroll
    for (int mi = 0; mi < 2; mi++)
        #pragma unroll
        for (int ni = 0; ni < 4; ni++)
            #pragma unroll
            for (int k = 0; k < 4; k++) c[mi][ni][k] = 0.f;

    const int S = K / BK;

    {
        #pragma unroll
        for (int i = 0; i < 2; i++) {
            int r = crow + i * 64;
            cp16(&As[0][r * ASTR + ccol], A + (size_t)(bm + r) * K + ccol);
        }
        cp16(&Bs[0][crow * ASTR + ccol], Bt + (size_t)(bn + crow) * K + ccol);
        cp_commit();
    }

    for (int s = 0; s < S; s++) {
        int buf = s & 1;
        if (s + 1 < S) {
            int nb = 1 - buf;
            int k0 = (s + 1) * BK;
            #pragma unroll
            for (int i = 0; i < 2; i++) {
                int r = crow + i * 64;
                cp16(&As[nb][r * ASTR + ccol], A + (size_t)(bm + r) * K + k0 + ccol);
            }
            cp16(&Bs[nb][crow * ASTR + ccol], Bt + (size_t)(bn + crow) * K + k0 + ccol);
            cp_commit();
            asm volatile("cp.async.wait_group 1;" ::: "memory");
        } else {
            asm volatile("cp.async.wait_group 0;" ::: "memory");
        }
        __syncthreads();

        const __nv_bfloat16* ab = &As[buf][(wm * 32) * ASTR];
        const __nv_bfloat16* bb = &Bs[buf][(wn * 32) * ASTR];

        #pragma unroll
        for (int ks = 0; ks < 2; ks++) {
            uint32_t af[2][4], bf[4][2];
            #pragma unroll
            for (int mi = 0; mi < 2; mi++) {
                const __nv_bfloat16* p0 = ab + (mi * 16 + g) * ASTR + ks * 16 + tig * 2;
                const __nv_bfloat16* p1 = p0 + 8 * ASTR;
                af[mi][0] = *(const uint32_t*)p0;
                af[mi][1] = *(const uint32_t*)p1;
                af[mi][2] = *(const uint32_t*)(p0 + 8);
                af[mi][3] = *(const uint32_t*)(p1 + 8);
            }
            #pragma unroll
            for (int ni = 0; ni < 4; ni++) {
                const __nv_bfloat16* p = bb + (ni * 8 + g) * ASTR + ks * 16 + tig * 2;
                bf[ni][0] = *(const uint32_t*)p;
                bf[ni][1] = *(const uint32_t*)(p + 8);
            }
            #pragma unroll
            for (int mi = 0; mi < 2; mi++)
                #pragma unroll
                for (int ni = 0; ni < 4; ni++)
                    mma16816(c[mi][ni], af[mi], bf[ni]);
        }
        __syncthreads();
    }

    #pragma unroll
    for (int mi = 0; mi < 2; mi++) {
        #pragma unroll
        for (int ni = 0; ni < 4; ni++) {
            int col = bn + wn * 32 + ni * 8 + tig * 2;
            float bv0 = bias[col], bv1 = bias[col + 1];
            #pragma unroll
            for (int half = 0; half < 2; half++) {
                int row = bm + wm * 32 + mi * 16 + g + half * 8;
                size_t gi = (size_t)row * N + col;
                float v0 = c[mi][ni][half * 2 + 0] + bv0;
                float v1 = c[mi][ni][half * 2 + 1] + bv1;
                if (EPI == 1) {
                    v0 = 0.5f * v0 * (1.0f + erff(v0 * 0.7071067811865476f));
                    v1 = 0.5f * v1 * (1.0f + erff(v1 * 0.7071067811865476f));
                } else if (EPI == 2) {
                    v0 += res[gi];
                    v1 += res[gi + 1];
                }
                stv(&C[gi], v0);
                stv(&C[gi + 1], v1);
            }
        }
    }
}

// --------------------- tensor-core flash attention ---------------------------
// CTA: 128 q-rows of one (b,h). 4 warps, each 32 q-rows. Keys in tiles of 64.
// S = Q@K^T via mma (Q,K bf16 K-major in SMEM), fp32 online softmax in regs,
// O += P@V via mma with P fragments taken directly from S accumulators.
#define AQ 128
#define AK 64
#define QSTR 40
#define VSTR 72
__global__ void __launch_bounds__(128) attn_mma(
    const __nv_bfloat16* __restrict__ qkvbf,
    const __nv_bfloat16* __restrict__ vt,
    __nv_bfloat16* __restrict__ out)
{
    __shared__ __nv_bfloat16 Qs[AQ * QSTR];
    __shared__ __nv_bfloat16 Ks[2][AK * QSTR];
    __shared__ __nv_bfloat16 Vs[2][HD * VSTR];

    int tid = threadIdx.x;
    int w = tid >> 5, lane = tid & 31;
    int g = lane >> 2, tig = lane & 3;
    int bh = blockIdx.y, b = bh >> 3, h = bh & 7;
    int qt = blockIdx.x;
    const float scale = 0.17677669529663687f;  // 1/sqrt(32)

    // Q: 128 rows x 64B
    {
        const char* src = (const char*)(qkvbf + ((size_t)(b * SEQ + qt * AQ)) * (3 * DIM) + h * HD);
        #pragma unroll
        for (int i = 0; i < 4; i++) {
            int cch = tid + i * 128;
            int row = cch >> 2, col = (cch & 3) * 8;
            cp16(&Qs[row * QSTR + col], src + (size_t)row * (3 * DIM * 2) + col * 2);
        }
    }
    // prime K/V tile 0 into buf 0
    {
        const char* ks = (const char*)(qkvbf + ((size_t)(b * SEQ)) * (3 * DIM) + DIM + h * HD);
        #pragma unroll
        for (int i = 0; i < 2; i++) {
            int cch = tid + i * 128;
            int row = cch >> 2, col = (cch & 3) * 8;
            cp16(&Ks[0][row * QSTR + col], ks + (size_t)row * (3 * DIM * 2) + col * 2);
        }
        const char* vs = (const char*)(vt + ((size_t)(bh * HD)) * SEQ);
        #pragma unroll
        for (int i = 0; i < 2; i++) {
            int cch = tid + i * 128;
            int d = cch >> 3, col = (cch & 7) * 8;
            cp16(&Vs[0][d * VSTR + col], vs + (size_t)d * (SEQ * 2) + col * 2);
        }
        cp_commit();
    }

    float o[2][4][4];
    #pragma unroll
    for (int mi = 0; mi < 2; mi++)
        #pragma unroll
        for (int nd = 0; nd < 4; nd++)
            #pragma unroll
            for (int k = 0; k < 4; k++) o[mi][nd][k] = 0.f;
    float mrow[2][2] = {{-1e30f, -1e30f}, {-1e30f, -1e30f}};
    float lrow[2][2] = {{0.f, 0.f}, {0.f, 0.f}};

    const int S = SEQ / AK;   // 32
    for (int s = 0; s < S; s++) {
        int buf = s & 1;
        if (s + 1 < S) {
            int nb = 1 - buf;
            const char* ks = (const char*)(qkvbf + ((size_t)(b * SEQ + (s + 1) * AK)) * (3 * DIM) + DIM + h * HD);
            #pragma unroll
            for (int i = 0; i < 2; i++) {
                int cch = tid + i * 128;
                int row = cch >> 2, col = (cch & 3) * 8;
                cp16(&Ks[nb][row * QSTR + col], ks + (size_t)row * (3 * DIM * 2) + col * 2);
            }
            const char* vs = (const char*)(vt + ((size_t)(bh * HD)) * SEQ + (s + 1) * AK);
            #pragma unroll
            for (int i = 0; i < 2; i++) {
                int cch = tid + i * 128;
                int d = cch >> 3, col = (cch & 7) * 8;
                cp16(&Vs[nb][d * VSTR + col], vs + (size_t)d * (SEQ * 2) + col * 2);
            }
            cp_commit();
            asm volatile("cp.async.wait_group 1;" ::: "memory");
        } else {
            asm volatile("cp.async.wait_group 0;" ::: "memory");
        }
        __syncthreads();

        #pragma unroll
        for (int mi = 0; mi < 2; mi++) {
            // ----- S = Q @ K^T for this 16-row tile, 64 cols -----
            float scv[8][4];
            #pragma unroll
            for (int ni = 0; ni < 8; ni++)
                #pragma unroll
                for (int k = 0; k < 4; k++) scv[ni][k] = 0.f;

            #pragma unroll
            for (int ks = 0; ks < 2; ks++) {
                uint32_t af[4];
                const __nv_bfloat16* qp = &Qs[(w * 32 + mi * 16 + g) * QSTR + ks * 16 + tig * 2];
                af[0] = *(const uint32_t*)qp;
                af[1] = *(const uint32_t*)(qp + 8 * QSTR);
                af[2] = *(const uint32_t*)(qp + 8);
                af[3] = *(const uint32_t*)(qp + 8 * QSTR + 8);
                #pragma unroll
                for (int ni = 0; ni < 8; ni++) {
                    const __nv_bfloat16* kp = &Ks[buf][(ni * 8 + g) * QSTR + ks * 16 + tig * 2];
                    uint32_t bf2[2] = { *(const uint32_t*)kp, *(const uint32_t*)(kp + 8) };
                    mma16816(scv[ni], af, bf2);
                }
            }

            // ----- online softmax (rows g and g+8) -----
            float mx0 = -1e30f, mx1 = -1e30f;
            #pragma unroll
            for (int ni = 0; ni < 8; ni++) {
                #pragma unroll
                for (int k = 0; k < 4; k++) scv[ni][k] *= scale;
                mx0 = fmaxf(mx0, fmaxf(scv[ni][0], scv[ni][1]));
                mx1 = fmaxf(mx1, fmaxf(scv[ni][2], scv[ni][3]));
            }
            mx0 = fmaxf(mx0, __shfl_xor_sync(0xffffffffu, mx0, 1));
            mx0 = fmaxf(mx0, __shfl_xor_sync(0xffffffffu, mx0, 2));
            mx1 = fmaxf(mx1, __shfl_xor_sync(0xffffffffu, mx1, 1));
            mx1 = fmaxf(mx1, __shfl_xor_sync(0xffffffffu, mx1, 2));

            float m0 = fmaxf(mrow[mi][0], mx0);
            float m1 = fmaxf(mrow[mi][1], mx1);
            float corr0 = __expf(mrow[mi][0] - m0);
            float corr1 = __expf(mrow[mi][1] - m1);
            mrow[mi][0] = m0; mrow[mi][1] = m1;

            float s0 = 0.f, s1 = 0.f;
            #pragma unroll
            for (int ni = 0; ni < 8; ni++) {
                scv[ni][0] = __expf(scv[ni][0] - m0);
                scv[ni][1] = __expf(scv[ni][1] - m0);
                scv[ni][2] = __expf(scv[ni][2] - m1);
                scv[ni][3] = __expf(scv[ni][3] - m1);
                s0 += scv[ni][0] + scv[ni][1];
                s1 += scv[ni][2] + scv[ni][3];
            }
            s0 += __shfl_xor_sync(0xffffffffu, s0, 1);
            s0 += __shfl_xor_sync(0xffffffffu, s0, 2);
            s1 += __shfl_xor_sync(0xffffffffu, s1, 1);
            s1 += __shfl_xor_sync(0xffffffffu, s1, 2);
            lrow[mi][0] = lrow[mi][0] * corr0 + s0;
            lrow[mi][1] = lrow[mi][1] * corr1 + s1;

            #pragma unroll
            for (int nd = 0; nd < 4; nd++) {
                o[mi][nd][0] *= corr0; o[mi][nd][1] *= corr0;
                o[mi][nd][2] *= corr1; o[mi][nd][3] *= corr1;
            }

            // ----- O += P @ V  (P fragments straight from S accumulators) -----
            #pragma unroll
            for (int ks2 = 0; ks2 < 4; ks2++) {
                uint32_t a[4];
                a[0] = pk(scv[2 * ks2][0],     scv[2 * ks2][1]);
                a[1] = pk(scv[2 * ks2][2],     scv[2 * ks2][3]);
                a[2] = pk(scv[2 * ks2 + 1][0], scv[2 * ks2 + 1][1]);
                a[3] = pk(scv[2 * ks2 + 1][2], scv[2 * ks2 + 1][3]);
                #pragma unroll
                for (int nd = 0; nd < 4; nd++) {
                    const __nv_bfloat16* vp = &Vs[buf][(nd * 8 + g) * VSTR + ks2 * 16 + tig * 2];
                    uint32_t bf2[2] = { *(const uint32_t*)vp, *(const uint32_t*)(vp + 8) };
                    mma16816(o[mi][nd], a, bf2);
                }
            }
        }
        __syncthreads();
    }

    // ----- write O -----
    #pragma unroll
    for (int mi = 0; mi < 2; mi++) {
        float i0 = 1.f / lrow[mi][0], i1 = 1.f / lrow[mi][1];
        int r0 = qt * AQ + w * 32 + mi * 16 + g;
        #pragma unroll
        for (int nd = 0; nd < 4; nd++) {
            int d = h * HD + nd * 8 + tig * 2;
            __nv_bfloat162 v0 = __floats2bfloat162_rn(o[mi][nd][0] * i0, o[mi][nd][1] * i0);
            __nv_bfloat162 v1 = __floats2bfloat162_rn(o[mi][nd][2] * i1, o[mi][nd][3] * i1);
            *(__nv_bfloat162*)&out[((size_t)(b * SEQ + r0)) * DIM + d] = v0;
            *(__nv_bfloat162*)&out[((size_t)(b * SEQ + r0 + 8)) * DIM + d] = v1;
        }
    }
}

// ------------------------------ host launch ---------------------------------
extern "C" void kernel_launch(void* const* d_in, const int* in_sizes, int n_in,
                              void* d_out, int out_size)
{
    const float* x     = (const float*)d_in[0];
    const float* ln1_g = (const float*)d_in[1] + LAYER * DIM;
    const float* ln1_b = (const float*)d_in[2] + LAYER * DIM;
    const float* Wqkv  = (const float*)d_in[3] + (size_t)LAYER * DIM * 3 * DIM;
    const float* bqkv  = (const float*)d_in[4] + LAYER * 3 * DIM;
    const float* Wo    = (const float*)d_in[5] + (size_t)LAYER * DIM * DIM;
    const float* bo    = (const float*)d_in[6] + LAYER * DIM;
    const float* ln2_g = (const float*)d_in[7] + LAYER * DIM;
    const float* ln2_b = (const float*)d_in[8] + LAYER * DIM;
    const float* W1    = (const float*)d_in[9] + (size_t)LAYER * DIM * MLPD;
    const float* b1    = (const float*)d_in[10] + LAYER * MLPD;
    const float* W2    = (const float*)d_in[11] + (size_t)LAYER * MLPD * DIM;
    const float* b2    = (const float*)d_in[12] + LAYER * DIM;
    float* out = (float*)d_out;

    __nv_bfloat16 *ybf, *qkvbf, *vtp, *attnbf, *zbf, *hbf, *WqkvT, *WoT, *W1T, *W2T;
    float *a;
    cudaGetSymbolAddress((void**)&ybf,    g_ybf);
    cudaGetSymbolAddress((void**)&qkvbf,  g_qkvbf);
    cudaGetSymbolAddress((void**)&vtp,    g_vt);
    cudaGetSymbolAddress((void**)&attnbf, g_attnbf);
    cudaGetSymbolAddress((void**)&a,      g_a);
    cudaGetSymbolAddress((void**)&zbf,    g_zbf);
    cudaGetSymbolAddress((void**)&hbf,    g_hbf);
    cudaGetSymbolAddress((void**)&WqkvT,  g_WqkvT);
    cudaGetSymbolAddress((void**)&WoT,    g_WoT);
    cudaGetSymbolAddress((void**)&W1T,    g_W1T);
    cudaGetSymbolAddress((void**)&W2T,    g_W2T);

    dim3 tb(32, 8);

    // 0. weights -> bf16 transposed [N][K]
    transpose_bf16<<<dim3(3 * DIM / 32, DIM / 32), tb>>>(Wqkv, WqkvT, DIM, 3 * DIM);
    transpose_bf16<<<dim3(DIM / 32, DIM / 32),     tb>>>(Wo,   WoT,   DIM, DIM);
    transpose_bf16<<<dim3(MLPD / 32, DIM / 32),    tb>>>(W1,   W1T,   DIM, MLPD);
    transpose_bf16<<<dim3(DIM / 32, MLPD / 32),    tb>>>(W2,   W2T,   MLPD, DIM);

    // 1. y = LN1(x)  (bf16)
    ln_kernel<__nv_bfloat16><<<ROWS, 256>>>(x, ln1_g, ln1_b, ybf);

    // 2. qkv = y @ Wqkv + bqkv           [4096 x 768]  (bf16 out)
    gemm_mma<0, __nv_bfloat16><<<dim3((3 * DIM) / BN, ROWS / BM), 256>>>(
        ybf, WqkvT, bqkv, nullptr, qkvbf, ROWS, 3 * DIM, DIM);

    // 2b. Vt per (b,h)
    transpose_v<<<dim3(SEQ / 64, BATCH * HEADS), tb>>>(qkvbf, vtp);

    // 3. attention (tensor cores)         [4096 x 256]  (bf16 out)
    attn_mma<<<dim3(SEQ / AQ, BATCH * HEADS), 128>>>(qkvbf, vtp, attnbf);

    // 4. a = attn @ Wo + bo + x           [4096 x 256]
    gemm_mma<2, float><<<dim3(DIM / BN, ROWS / BM), 256>>>(
        attnbf, WoT, bo, x, a, ROWS, DIM, DIM);

    // 5. z = LN2(a)  (bf16)
    ln_kernel<__nv_bfloat16><<<ROWS, 256>>>(a, ln2_g, ln2_b, zbf);

    // 6. h = gelu(z @ W1 + b1)            [4096 x 1024]  (bf16 out)
    gemm_mma<1, __nv_bfloat16><<<dim3(MLPD / BN, ROWS / BM), 256>>>(
        zbf, W1T, b1, nullptr, hbf, ROWS, MLPD, DIM);

    // 7. out = h @ W2 + b2 + a            [4096 x 256]
    gemm_mma<2, float><<<dim3(DIM / BN, ROWS / BM), 256>>>(
        hbf, W2T, b2, a, out, ROWS, DIM, MLPD);
}

// round 17
// speedup vs baseline: 1.1603x; 1.1603x over previous
#include <cuda_runtime.h>
#include <cuda_bf16.h>
#include <math.h>
#include <stdint.h>

// Problem constants (DEPTH=2, but reference returns only last layer's output
// computed from the ORIGINAL x, so we evaluate ONLY layer index 1).
#define BATCH 2
#define SEQ   2048
#define DIM   256
#define MLPD  1024
#define HEADS 8
#define HD    32
#define ROWS  (BATCH*SEQ)          // 4096
#define LAYER 1

// ------------------------- scratch (device globals) -------------------------
__device__ __nv_bfloat16 g_ybf   [ROWS*DIM];       // ln1 out (bf16)
__device__ __nv_bfloat16 g_qkvbf [ROWS*3*DIM];     // qkv (bf16)
__device__ __nv_bfloat16 g_vt    [BATCH*HEADS*HD*SEQ]; // V^T per (b,h): [bh][32][2048]
__device__ __nv_bfloat16 g_attnbf[ROWS*DIM];       // attention out (bf16)
__device__ float         g_a     [ROWS*DIM];       // attn residual (fp32)
__device__ __nv_bfloat16 g_zbf   [ROWS*DIM];       // ln2 out (bf16)
__device__ __nv_bfloat16 g_hbf   [ROWS*MLPD];      // mlp hidden (bf16)
// transposed bf16 weights  [N][K]
__device__ __nv_bfloat16 g_WqkvT [3*DIM*DIM];
__device__ __nv_bfloat16 g_WoT   [DIM*DIM];
__device__ __nv_bfloat16 g_W1T   [MLPD*DIM];
__device__ __nv_bfloat16 g_W2T   [DIM*MLPD];

// ----------------------------- helpers --------------------------------------
__device__ __forceinline__ void cp16(void* sdst, const void* gsrc) {
    uint32_t s = (uint32_t)__cvta_generic_to_shared(sdst);
    asm volatile("cp.async.cg.shared.global [%0], [%1], 16;"
                 :: "r"(s), "l"(gsrc) : "memory");
}
__device__ __forceinline__ void cp_commit() {
    asm volatile("cp.async.commit_group;" ::: "memory");
}
__device__ __forceinline__ void mma16816(float* c, const uint32_t* a,
                                         const uint32_t* b) {
    asm volatile(
        "mma.sync.aligned.m16n8k16.row.col.f32.bf16.bf16.f32 "
        "{%0,%1,%2,%3}, {%4,%5,%6,%7}, {%8,%9}, {%0,%1,%2,%3};"
        : "+f"(c[0]), "+f"(c[1]), "+f"(c[2]), "+f"(c[3])
        : "r"(a[0]), "r"(a[1]), "r"(a[2]), "r"(a[3]), "r"(b[0]), "r"(b[1]));
}
__device__ __forceinline__ void ldmx4(uint32_t* r, const void* p) {
    uint32_t a = (uint32_t)__cvta_generic_to_shared(p);
    asm volatile("ldmatrix.sync.aligned.m8n8.x4.shared.b16 {%0,%1,%2,%3}, [%4];"
                 : "=r"(r[0]), "=r"(r[1]), "=r"(r[2]), "=r"(r[3]) : "r"(a));
}
__device__ __forceinline__ uint32_t pk(float lo, float hi) {
    __nv_bfloat162 t = __floats2bfloat162_rn(lo, hi);
    return *(uint32_t*)&t;
}
__device__ __forceinline__ float ex2(float x) {
    float r; asm("ex2.approx.f32 %0, %1;" : "=f"(r) : "f"(x)); return r;
}

// output store helpers
__device__ __forceinline__ void stv(float* p, float v) { *p = v; }
__device__ __forceinline__ void stv(__nv_bfloat16* p, float v) { *p = __float2bfloat16(v); }

// ------------------------------ LayerNorm -----------------------------------
// 8 warps/block, one row per warp, float4 loads/stores.
__global__ void ln_kernel(const float* __restrict__ x,
                          const float* __restrict__ gamma,
                          const float* __restrict__ beta,
                          __nv_bfloat16* __restrict__ y)
{
    int row  = blockIdx.x * 8 + (threadIdx.x >> 5);
    int lane = threadIdx.x & 31;
    const float4* xr = (const float4*)(x + (size_t)row * DIM);
    float4 v0 = xr[lane * 2], v1 = xr[lane * 2 + 1];

    float s  = v0.x + v0.y + v0.z + v0.w + v1.x + v1.y + v1.z + v1.w;
    float sq = v0.x*v0.x + v0.y*v0.y + v0.z*v0.z + v0.w*v0.w
             + v1.x*v1.x + v1.y*v1.y + v1.z*v1.z + v1.w*v1.w;
    #pragma unroll
    for (int o = 16; o; o >>= 1) {
        s  += __shfl_xor_sync(0xffffffffu, s,  o);
        sq += __shfl_xor_sync(0xffffffffu, sq, o);
    }
    float mean = s * (1.0f / DIM);
    float var  = sq * (1.0f / DIM) - mean * mean;
    float inv  = rsqrtf(var + 1e-5f);

    const float4* gr = (const float4*)gamma;
    const float4* br = (const float4*)beta;
    float4 gA = gr[lane * 2], gB = gr[lane * 2 + 1];
    float4 bA = br[lane * 2], bB = br[lane * 2 + 1];

    __nv_bfloat162 o2[4];
    o2[0] = __floats2bfloat162_rn((v0.x - mean) * inv * gA.x + bA.x,
                                  (v0.y - mean) * inv * gA.y + bA.y);
    o2[1] = __floats2bfloat162_rn((v0.z - mean) * inv * gA.z + bA.z,
                                  (v0.w - mean) * inv * gA.w + bA.w);
    o2[2] = __floats2bfloat162_rn((v1.x - mean) * inv * gB.x + bB.x,
                                  (v1.y - mean) * inv * gB.y + bB.y);
    o2[3] = __floats2bfloat162_rn((v1.z - mean) * inv * gB.z + bB.z,
                                  (v1.w - mean) * inv * gB.w + bB.w);
    *(uint4*)&y[(size_t)row * DIM + lane * 8] = *(uint4*)o2;
}

// ----------- all 4 weight transposes (fp32 [R][C] -> bf16 [C][R]) ------------
__global__ void transpose_all(const float* __restrict__ Wqkv,
                              const float* __restrict__ Wo,
                              const float* __restrict__ W1,
                              const float* __restrict__ W2,
                              __nv_bfloat16* __restrict__ WqkvT,
                              __nv_bfloat16* __restrict__ WoT,
                              __nv_bfloat16* __restrict__ W1T,
                              __nv_bfloat16* __restrict__ W2T)
{
    __shared__ float t[32][33];
    int id = blockIdx.x;
    const float* in; __nv_bfloat16* outp; int R, C, lt;
    if (id < 192)      { in = Wqkv; outp = WqkvT; R = 256;  C = 768;  lt = id; }
    else if (id < 256) { in = Wo;   outp = WoT;   R = 256;  C = 256;  lt = id - 192; }
    else if (id < 512) { in = W1;   outp = W1T;   R = 256;  C = 1024; lt = id - 256; }
    else               { in = W2;   outp = W2T;   R = 1024; C = 256;  lt = id - 512; }
    int tc = C >> 5;
    int c0 = (lt % tc) * 32, r0 = (lt / tc) * 32;
    int tx = threadIdx.x, ty = threadIdx.y;   // (32, 8)
    #pragma unroll
    for (int i = 0; i < 32; i += 8)
        t[ty + i][tx] = in[(size_t)(r0 + ty + i) * C + c0 + tx];
    __syncthreads();
    #pragma unroll
    for (int i = 0; i < 32; i += 8)
        outp[(size_t)(c0 + ty + i) * R + r0 + tx] = __float2bfloat16(t[tx][ty + i]);
}

// ------------------------- mma.sync bf16 GEMM --------------------------------
// C[M,N] = A[M,K] @ Bt[N,K]^T + bias[N]  (+ epilogue)
// EPI: 0 = bias, 1 = bias + exact GELU, 2 = bias + residual
// VT:  also scatter V columns (col>=512 of the QKV output) into g_vt layout.
#define BM 128
#define BN 64
#define BK 32
#define ASTR 40   // bf16 elems per smem row (32 data + 8 pad) -> 80B stride
template <int EPI, bool VT, typename OT>
__global__ void __launch_bounds__(256) gemm_mma(
    const __nv_bfloat16* __restrict__ A,
    const __nv_bfloat16* __restrict__ Bt,
    const float* __restrict__ bias,
    const float* __restrict__ res,
    OT* __restrict__ C,
    __nv_bfloat16* __restrict__ vt,
    int M, int N, int K)
{
    __shared__ __nv_bfloat16 As[2][BM * ASTR];
    __shared__ __nv_bfloat16 Bs[2][BN * ASTR];

    int tid = threadIdx.x;
    int wid = tid >> 5, lane = tid & 31;
    int wm = wid & 3, wn = wid >> 2;     // 4 x 2 warp grid
    int g = lane >> 2, tig = lane & 3;
    int l8 = lane & 7, lt = lane >> 3;
    int bm = blockIdx.y * BM, bn = blockIdx.x * BN;

    int crow = tid >> 2;
    int ccol = (tid & 3) * 8;

    float c[2][4][4];
    #pragma unroll
    for (int mi = 0; mi < 2; mi++)
        #pragma unroll
        for (int ni = 0; ni < 4; ni++)
            #pragma unroll
            for (int k = 0; k < 4; k++) c[mi][ni][k] = 0.f;

    const int S = K / BK;

    {
        #pragma unroll
        for (int i = 0; i < 2; i++) {
            int r = crow + i * 64;
            cp16(&As[0][r * ASTR + ccol], A + (size_t)(bm + r) * K + ccol);
        }
        cp16(&Bs[0][crow * ASTR + ccol], Bt + (size_t)(bn + crow) * K + ccol);
        cp_commit();
    }

    for (int s = 0; s < S; s++) {
        int buf = s & 1;
        if (s + 1 < S) {
            int nb = 1 - buf;
            int k0 = (s + 1) * BK;
            #pragma unroll
            for (int i = 0; i < 2; i++) {
                int r = crow + i * 64;
                cp16(&As[nb][r * ASTR + ccol], A + (size_t)(bm + r) * K + k0 + ccol);
            }
            cp16(&Bs[nb][crow * ASTR + ccol], Bt + (size_t)(bn + crow) * K + k0 + ccol);
            cp_commit();
            asm volatile("cp.async.wait_group 1;" ::: "memory");
        } else {
            asm volatile("cp.async.wait_group 0;" ::: "memory");
        }
        __syncthreads();

        const __nv_bfloat16* ab = &As[buf][(wm * 32) * ASTR];
        const __nv_bfloat16* bb = &Bs[buf][(wn * 32) * ASTR];

        #pragma unroll
        for (int ks = 0; ks < 2; ks++) {
            uint32_t af[2][4], bf[2][4];
            #pragma unroll
            for (int mi = 0; mi < 2; mi++)
                ldmx4(af[mi],
                      ab + (mi * 16 + (lt & 1) * 8 + l8) * ASTR + ks * 16 + (lt >> 1) * 8);
            #pragma unroll
            for (int gb = 0; gb < 2; gb++)
                ldmx4(bf[gb],
                      bb + ((gb * 2 + (lt >> 1)) * 8 + l8) * ASTR + ks * 16 + (lt & 1) * 8);
            #pragma unroll
            for (int mi = 0; mi < 2; mi++)
                #pragma unroll
                for (int ni = 0; ni < 4; ni++)
                    mma16816(c[mi][ni], af[mi], &bf[ni >> 1][(ni & 1) * 2]);
        }
        __syncthreads();
    }

    #pragma unroll
    for (int mi = 0; mi < 2; mi++) {
        #pragma unroll
        for (int ni = 0; ni < 4; ni++) {
            int col = bn + wn * 32 + ni * 8 + tig * 2;
            float bv0 = bias[col], bv1 = bias[col + 1];
            #pragma unroll
            for (int half = 0; half < 2; half++) {
                int row = bm + wm * 32 + mi * 16 + g + half * 8;
                size_t gi = (size_t)row * N + col;
                float v0 = c[mi][ni][half * 2 + 0] + bv0;
                float v1 = c[mi][ni][half * 2 + 1] + bv1;
                if (EPI == 1) {
                    v0 = 0.5f * v0 * (1.0f + erff(v0 * 0.7071067811865476f));
                    v1 = 0.5f * v1 * (1.0f + erff(v1 * 0.7071067811865476f));
                } else if (EPI == 2) {
                    v0 += res[gi];
                    v1 += res[gi + 1];
                }
                stv(&C[gi], v0);
                stv(&C[gi + 1], v1);
                if (VT && col >= 2 * DIM) {
                    // V column: also write transposed copy for attention's P@V.
                    int h = (col - 2 * DIM) >> 5;
                    int d = (col - 2 * DIM) & 31;
                    int b = row >> 11, n = row & (SEQ - 1);
                    __nv_bfloat16* vp =
                        vt + ((size_t)((b * HEADS + h) * HD + d)) * SEQ + n;
                    *vp = __float2bfloat16(v0);
                    *(vp + SEQ) = __float2bfloat16(v1);
                }
            }
        }
    }
}

// --------------------- tensor-core flash attention ---------------------------
// CTA: 128 q-rows of one (b,h). 4 warps x 32 q-rows. Keys in tiles of 64.
// Q fragments hoisted to registers; K/V fragments via ldmatrix; softmax in
// exp2 space with scale folded into the exponent (max tracked unscaled).
#define AQ 128
#define AK 64
#define QSTR 40
#define VSTR 72
#define SC2  0.2550052525592539f   // (1/sqrt(32)) * log2(e)
__global__ void __launch_bounds__(128) attn_mma(
    const __nv_bfloat16* __restrict__ qkvbf,
    const __nv_bfloat16* __restrict__ vt,
    __nv_bfloat16* __restrict__ out)
{
    __shared__ __nv_bfloat16 Qs[AQ * QSTR];
    __shared__ __nv_bfloat16 Ks[2][AK * QSTR];
    __shared__ __nv_bfloat16 Vs[2][HD * VSTR];

    int tid = threadIdx.x;
    int w = tid >> 5, lane = tid & 31;
    int g = lane >> 2, tig = lane & 3;
    int l8 = lane & 7, lt = lane >> 3;
    int bh = blockIdx.y, b = bh >> 3, h = bh & 7;
    int qt = blockIdx.x;

    // Q: 128 rows x 64B (group A)
    {
        const char* src = (const char*)(qkvbf + ((size_t)(b * SEQ + qt * AQ)) * (3 * DIM) + h * HD);
        #pragma unroll
        for (int i = 0; i < 4; i++) {
            int cch = tid + i * 128;
            int row = cch >> 2, col = (cch & 3) * 8;
            cp16(&Qs[row * QSTR + col], src + (size_t)row * (3 * DIM * 2) + col * 2);
        }
        cp_commit();
    }
    // K/V tile 0 (group B)
    {
        const char* ks = (const char*)(qkvbf + ((size_t)(b * SEQ)) * (3 * DIM) + DIM + h * HD);
        #pragma unroll
        for (int i = 0; i < 2; i++) {
            int cch = tid + i * 128;
            int row = cch >> 2, col = (cch & 3) * 8;
            cp16(&Ks[0][row * QSTR + col], ks + (size_t)row * (3 * DIM * 2) + col * 2);
        }
        const char* vs = (const char*)(vt + ((size_t)(bh * HD)) * SEQ);
        #pragma unroll
        for (int i = 0; i < 2; i++) {
            int cch = tid + i * 128;
            int d = cch >> 3, col = (cch & 7) * 8;
            cp16(&Vs[0][d * VSTR + col], vs + (size_t)d * (SEQ * 2) + col * 2);
        }
        cp_commit();
    }

    // hoist Q fragments into registers (loop-invariant)
    asm volatile("cp.async.wait_group 1;" ::: "memory");   // group A (Q) done
    __syncthreads();
    uint32_t qf[2][2][4];
    #pragma unroll
    for (int mi = 0; mi < 2; mi++)
        #pragma unroll
        for (int ks = 0; ks < 2; ks++)
            ldmx4(qf[mi][ks],
                  &Qs[(w * 32 + mi * 16 + (lt & 1) * 8 + l8) * QSTR + ks * 16 + (lt >> 1) * 8]);

    float o[2][4][4];
    #pragma unroll
    for (int mi = 0; mi < 2; mi++)
        #pragma unroll
        for (int nd = 0; nd < 4; nd++)
            #pragma unroll
            for (int k = 0; k < 4; k++) o[mi][nd][k] = 0.f;
    float mrow[2][2] = {{-1e30f, -1e30f}, {-1e30f, -1e30f}};   // UNSCALED max
    float lrow[2][2] = {{0.f, 0.f}, {0.f, 0.f}};

    const int S = SEQ / AK;   // 32
    for (int s = 0; s < S; s++) {
        int buf = s & 1;
        if (s + 1 < S) {
            int nb = 1 - buf;
            const char* ks = (const char*)(qkvbf + ((size_t)(b * SEQ + (s + 1) * AK)) * (3 * DIM) + DIM + h * HD);
            #pragma unroll
            for (int i = 0; i < 2; i++) {
                int cch = tid + i * 128;
                int row = cch >> 2, col = (cch & 3) * 8;
                cp16(&Ks[nb][row * QSTR + col], ks + (size_t)row * (3 * DIM * 2) + col * 2);
            }
            const char* vs = (const char*)(vt + ((size_t)(bh * HD)) * SEQ + (s + 1) * AK);
            #pragma unroll
            for (int i = 0; i < 2; i++) {
                int cch = tid + i * 128;
                int d = cch >> 3, col = (cch & 7) * 8;
                cp16(&Vs[nb][d * VSTR + col], vs + (size_t)d * (SEQ * 2) + col * 2);
            }
            cp_commit();
            asm volatile("cp.async.wait_group 1;" ::: "memory");
        } else {
            asm volatile("cp.async.wait_group 0;" ::: "memory");
        }
        __syncthreads();

        // K fragments: shared by both mi tiles
        uint32_t kf[2][8][2];
        #pragma unroll
        for (int ks = 0; ks < 2; ks++)
            #pragma unroll
            for (int gb = 0; gb < 4; gb++)
                ldmx4(&kf[ks][gb * 2][0],
                      &Ks[buf][((gb * 2 + (lt >> 1)) * 8 + l8) * QSTR + ks * 16 + (lt & 1) * 8]);

        #pragma unroll
        for (int mi = 0; mi < 2; mi++) {
            // ----- S = Q @ K^T (16 rows x 64 cols) -----
            float scv[8][4];
            #pragma unroll
            for (int ni = 0; ni < 8; ni++)
                #pragma unroll
                for (int k = 0; k < 4; k++) scv[ni][k] = 0.f;
            #pragma unroll
            for (int ks = 0; ks < 2; ks++)
                #pragma unroll
                for (int ni = 0; ni < 8; ni++)
                    mma16816(scv[ni], qf[mi][ks], kf[ks][ni]);

            // ----- online softmax in exp2 space (max unscaled) -----
            float mx0 = -1e30f, mx1 = -1e30f;
            #pragma unroll
            for (int ni = 0; ni < 8; ni++) {
                mx0 = fmaxf(mx0, fmaxf(scv[ni][0], scv[ni][1]));
                mx1 = fmaxf(mx1, fmaxf(scv[ni][2], scv[ni][3]));
            }
            mx0 = fmaxf(mx0, __shfl_xor_sync(0xffffffffu, mx0, 1));
            mx0 = fmaxf(mx0, __shfl_xor_sync(0xffffffffu, mx0, 2));
            mx1 = fmaxf(mx1, __shfl_xor_sync(0xffffffffu, mx1, 1));
            mx1 = fmaxf(mx1, __shfl_xor_sync(0xffffffffu, mx1, 2));

            float m0 = fmaxf(mrow[mi][0], mx0);
            float m1 = fmaxf(mrow[mi][1], mx1);
            float corr0 = ex2((mrow[mi][0] - m0) * SC2);
            float corr1 = ex2((mrow[mi][1] - m1) * SC2);
            mrow[mi][0] = m0; mrow[mi][1] = m1;
            float nm0 = -m0 * SC2, nm1 = -m1 * SC2;

            float s0 = 0.f, s1 = 0.f;
            #pragma unroll
            for (int ni = 0; ni < 8; ni++) {
                scv[ni][0] = ex2(fmaf(scv[ni][0], SC2, nm0));
                scv[ni][1] = ex2(fmaf(scv[ni][1], SC2, nm0));
                scv[ni][2] = ex2(fmaf(scv[ni][2], SC2, nm1));
                scv[ni][3] = ex2(fmaf(scv[ni][3], SC2, nm1));
                s0 += scv[ni][0] + scv[ni][1];
                s1 += scv[ni][2] + scv[ni][3];
            }
            s0 += __shfl_xor_sync(0xffffffffu, s0, 1);
            s0 += __shfl_xor_sync(0xffffffffu, s0, 2);
            s1 += __shfl_xor_sync(0xffffffffu, s1, 1);
            s1 += __shfl_xor_sync(0xffffffffu, s1, 2);
            lrow[mi][0] = lrow[mi][0] * corr0 + s0;
            lrow[mi][1] = lrow[mi][1] * corr1 + s1;

            #pragma unroll
            for (int nd = 0; nd < 4; nd++) {
                o[mi][nd][0] *= corr0; o[mi][nd][1] *= corr0;
                o[mi][nd][2] *= corr1; o[mi][nd][3] *= corr1;
            }

            // ----- O += P @ V  (P fragments straight from S accumulators) -----
            #pragma unroll
            for (int ks2 = 0; ks2 < 4; ks2++) {
                uint32_t a[4];
                a[0] = pk(scv[2 * ks2][0],     scv[2 * ks2][1]);
                a[1] = pk(scv[2 * ks2][2],     scv[2 * ks2][3]);
                a[2] = pk(scv[2 * ks2 + 1][0], scv[2 * ks2 + 1][1]);
                a[3] = pk(scv[2 * ks2 + 1][2], scv[2 * ks2 + 1][3]);
                uint32_t vfa[4], vfb[4];
                ldmx4(vfa, &Vs[buf][((lt >> 1) * 8 + l8) * VSTR + ks2 * 16 + (lt & 1) * 8]);
                ldmx4(vfb, &Vs[buf][((2 + (lt >> 1)) * 8 + l8) * VSTR + ks2 * 16 + (lt & 1) * 8]);
                mma16816(o[mi][0], a, vfa);
                mma16816(o[mi][1], a, vfa + 2);
                mma16816(o[mi][2], a, vfb);
                mma16816(o[mi][3], a, vfb + 2);
            }
        }
        __syncthreads();
    }

    // ----- write O -----
    #pragma unroll
    for (int mi = 0; mi < 2; mi++) {
        float i0 = 1.f / lrow[mi][0], i1 = 1.f / lrow[mi][1];
        int r0 = qt * AQ + w * 32 + mi * 16 + g;
        #pragma unroll
        for (int nd = 0; nd < 4; nd++) {
            int d = h * HD + nd * 8 + tig * 2;
            __nv_bfloat162 v0 = __floats2bfloat162_rn(o[mi][nd][0] * i0, o[mi][nd][1] * i0);
            __nv_bfloat162 v1 = __floats2bfloat162_rn(o[mi][nd][2] * i1, o[mi][nd][3] * i1);
            *(__nv_bfloat162*)&out[((size_t)(b * SEQ + r0)) * DIM + d] = v0;
            *(__nv_bfloat162*)&out[((size_t)(b * SEQ + r0 + 8)) * DIM + d] = v1;
        }
    }
}

// ------------------------------ host launch ---------------------------------
extern "C" void kernel_launch(void* const* d_in, const int* in_sizes, int n_in,
                              void* d_out, int out_size)
{
    const float* x     = (const float*)d_in[0];
    const float* ln1_g = (const float*)d_in[1] + LAYER * DIM;
    const float* ln1_b = (const float*)d_in[2] + LAYER * DIM;
    const float* Wqkv  = (const float*)d_in[3] + (size_t)LAYER * DIM * 3 * DIM;
    const float* bqkv  = (const float*)d_in[4] + LAYER * 3 * DIM;
    const float* Wo    = (const float*)d_in[5] + (size_t)LAYER * DIM * DIM;
    const float* bo    = (const float*)d_in[6] + LAYER * DIM;
    const float* ln2_g = (const float*)d_in[7] + LAYER * DIM;
    const float* ln2_b = (const float*)d_in[8] + LAYER * DIM;
    const float* W1    = (const float*)d_in[9] + (size_t)LAYER * DIM * MLPD;
    const float* b1    = (const float*)d_in[10] + LAYER * MLPD;
    const float* W2    = (const float*)d_in[11] + (size_t)LAYER * MLPD * DIM;
    const float* b2    = (const float*)d_in[12] + LAYER * DIM;
    float* out = (float*)d_out;

    __nv_bfloat16 *ybf, *qkvbf, *vtp, *attnbf, *zbf, *hbf, *WqkvT, *WoT, *W1T, *W2T;
    float *a;
    cudaGetSymbolAddress((void**)&ybf,    g_ybf);
    cudaGetSymbolAddress((void**)&qkvbf,  g_qkvbf);
    cudaGetSymbolAddress((void**)&vtp,    g_vt);
    cudaGetSymbolAddress((void**)&attnbf, g_attnbf);
    cudaGetSymbolAddress((void**)&a,      g_a);
    cudaGetSymbolAddress((void**)&zbf,    g_zbf);
    cudaGetSymbolAddress((void**)&hbf,    g_hbf);
    cudaGetSymbolAddress((void**)&WqkvT,  g_WqkvT);
    cudaGetSymbolAddress((void**)&WoT,    g_WoT);
    cudaGetSymbolAddress((void**)&W1T,    g_W1T);
    cudaGetSymbolAddress((void**)&W2T,    g_W2T);

    // 0. all weight transposes in one launch
    transpose_all<<<768, dim3(32, 8)>>>(Wqkv, Wo, W1, W2, WqkvT, WoT, W1T, W2T);

    // 1. y = LN1(x)  (bf16)
    ln_kernel<<<ROWS / 8, 256>>>(x, ln1_g, ln1_b, ybf);

    // 2. qkv = y @ Wqkv + bqkv  [4096 x 768] (bf16), V also scattered into vt
    gemm_mma<0, true, __nv_bfloat16><<<dim3((3 * DIM) / BN, ROWS / BM), 256>>>(
        ybf, WqkvT, bqkv, nullptr, qkvbf, vtp, ROWS, 3 * DIM, DIM);

    // 3. attention (tensor cores)         [4096 x 256]  (bf16 out)
    attn_mma<<<dim3(SEQ / AQ, BATCH * HEADS), 128>>>(qkvbf, vtp, attnbf);

    // 4. a = attn @ Wo + bo + x           [4096 x 256]
    gemm_mma<2, false, float><<<dim3(DIM / BN, ROWS / BM), 256>>>(
        attnbf, WoT, bo, x, a, nullptr, ROWS, DIM, DIM);

    // 5. z = LN2(a)  (bf16)
    ln_kernel<<<ROWS / 8, 256>>>(a, ln2_g, ln2_b, zbf);

    // 6. h = gelu(z @ W1 + b1)            [4096 x 1024]  (bf16 out)
    gemm_mma<1, false, __nv_bfloat16><<<dim3(MLPD / BN, ROWS / BM), 256>>>(
        zbf, W1T, b1, nullptr, hbf, nullptr, ROWS, MLPD, DIM);

    // 7. out = h @ W2 + b2 + a            [4096 x 256]
    gemm_mma<2, false, float><<<dim3(DIM / BN, ROWS / BM), 256>>>(
        hbf, W2T, b2, a, out, nullptr, ROWS, DIM, MLPD);
}